// round 2
// baseline (speedup 1.0000x reference)
#include <cuda_runtime.h>

#define E_DIM 8
#define F_DIM 32
#define TPT 2          // tokens per thread
#define THREADS 256

using u64 = unsigned long long;

__device__ __forceinline__ u64 pack2(float lo, float hi) {
    u64 r;
    asm("mov.b64 %0, {%1, %2};" : "=l"(r) : "f"(lo), "f"(hi));
    return r;
}
__device__ __forceinline__ void unpack2(u64 v, float& lo, float& hi) {
    asm("mov.b64 {%0, %1}, %2;" : "=f"(lo), "=f"(hi) : "l"(v));
}
// Packed dual fp32 FMA (Blackwell f32x2 pipe, 2x scalar FFMA throughput).
__device__ __forceinline__ u64 fma2(u64 a, u64 b, u64 c) {
    u64 d;
    asm("fma.rn.f32x2 %0, %1, %2, %3;" : "=l"(d) : "l"(a), "l"(b), "l"(c));
    return d;
}

__global__ void __launch_bounds__(THREADS)
ffq_kernel(const float* __restrict__ x,
           const float* __restrict__ theta,
           const float* __restrict__ w1,   // [E, F] row-major
           const float* __restrict__ b1,   // [F]
           const float* __restrict__ w2,   // [F, E] row-major
           const float* __restrict__ b2,   // [E]
           float* __restrict__ out,
           int n_tokens)
{
    // Weights as packed fp32 pairs (pairs are contiguous in gmem, so raw
    // 64-bit copies give the packing for free).
    __shared__ u64 sw1[E_DIM * (F_DIM / 2)];  // [i][f2], 128 entries
    __shared__ u64 sb1[F_DIM / 2];            // 16
    __shared__ u64 sw2[F_DIM * (E_DIM / 2)];  // [f][e2], 128 entries
    __shared__ u64 sb2[E_DIM / 2];            // 4
    __shared__ float sth[E_DIM];

    const int t = threadIdx.x;
    if (t < 128)                sw1[t]       = ((const u64*)w1)[t];
    else                        sw2[t - 128] = ((const u64*)w2)[t - 128];
    if (t < 16)                 sb1[t]       = ((const u64*)b1)[t];
    else if (t < 20)            sb2[t - 16]  = ((const u64*)b2)[t - 16];
    else if (t < 28)            sth[t - 20]  = theta[t - 20];
    __syncthreads();

    const long long pair = (long long)blockIdx.x * THREADS + t;
    const long long token0 = pair * TPT;
    if (token0 + 1 >= n_tokens) return;   // n_tokens is even; exact grid

    // ---- load x for 2 tokens: 64 contiguous bytes ----
    const float4* xp = (const float4*)(x + token0 * E_DIM);
    float4 a0 = xp[0], a1 = xp[1], a2 = xp[2], a3 = xp[3];

    // ---- quantum layer: q = cos(x + theta) ----
    float q0[E_DIM], q1[E_DIM];
    q0[0] = __cosf(a0.x + sth[0]); q0[1] = __cosf(a0.y + sth[1]);
    q0[2] = __cosf(a0.z + sth[2]); q0[3] = __cosf(a0.w + sth[3]);
    q0[4] = __cosf(a1.x + sth[4]); q0[5] = __cosf(a1.y + sth[5]);
    q0[6] = __cosf(a1.z + sth[6]); q0[7] = __cosf(a1.w + sth[7]);
    q1[0] = __cosf(a2.x + sth[0]); q1[1] = __cosf(a2.y + sth[1]);
    q1[2] = __cosf(a2.z + sth[2]); q1[3] = __cosf(a2.w + sth[3]);
    q1[4] = __cosf(a3.x + sth[4]); q1[5] = __cosf(a3.y + sth[5]);
    q1[6] = __cosf(a3.z + sth[6]); q1[7] = __cosf(a3.w + sth[7]);

    // ---- layer 1: h = relu(q @ W1 + b1), packed over F pairs ----
    u64 h0[F_DIM / 2], h1[F_DIM / 2];
#pragma unroll
    for (int f2 = 0; f2 < F_DIM / 2; f2++) {
        u64 b = sb1[f2];
        h0[f2] = b; h1[f2] = b;
    }
#pragma unroll
    for (int i = 0; i < E_DIM; i++) {
        u64 qa = pack2(q0[i], q0[i]);
        u64 qb = pack2(q1[i], q1[i]);
#pragma unroll
        for (int f2 = 0; f2 < F_DIM / 2; f2++) {
            u64 w = sw1[i * (F_DIM / 2) + f2];   // one LDS serves both tokens
            h0[f2] = fma2(qa, w, h0[f2]);
            h1[f2] = fma2(qb, w, h1[f2]);
        }
    }

    // ---- layer 2: out = h @ W2 + b2, packed over E pairs ----
    u64 o0[E_DIM / 2], o1[E_DIM / 2];
#pragma unroll
    for (int e2 = 0; e2 < E_DIM / 2; e2++) {
        u64 b = sb2[e2];
        o0[e2] = b; o1[e2] = b;
    }
#pragma unroll
    for (int f2 = 0; f2 < F_DIM / 2; f2++) {
        float h0lo, h0hi, h1lo, h1hi;
        unpack2(h0[f2], h0lo, h0hi);
        unpack2(h1[f2], h1lo, h1hi);
        h0lo = fmaxf(h0lo, 0.0f); h0hi = fmaxf(h0hi, 0.0f);
        h1lo = fmaxf(h1lo, 0.0f); h1hi = fmaxf(h1hi, 0.0f);
        u64 d0lo = pack2(h0lo, h0lo), d0hi = pack2(h0hi, h0hi);
        u64 d1lo = pack2(h1lo, h1lo), d1hi = pack2(h1hi, h1hi);
        const int f = 2 * f2;
#pragma unroll
        for (int e2 = 0; e2 < E_DIM / 2; e2++) {
            u64 wlo = sw2[f * (E_DIM / 2) + e2];        // shared by both tokens
            u64 whi = sw2[(f + 1) * (E_DIM / 2) + e2];
            o0[e2] = fma2(d0lo, wlo, o0[e2]);
            o0[e2] = fma2(d0hi, whi, o0[e2]);
            o1[e2] = fma2(d1lo, wlo, o1[e2]);
            o1[e2] = fma2(d1hi, whi, o1[e2]);
        }
    }

    // ---- store 2 tokens: 64 contiguous bytes ----
    float4 r0, r1, r2, r3;
    unpack2(o0[0], r0.x, r0.y); unpack2(o0[1], r0.z, r0.w);
    unpack2(o0[2], r1.x, r1.y); unpack2(o0[3], r1.z, r1.w);
    unpack2(o1[0], r2.x, r2.y); unpack2(o1[1], r2.z, r2.w);
    unpack2(o1[2], r3.x, r3.y); unpack2(o1[3], r3.z, r3.w);
    float4* op = (float4*)(out + token0 * E_DIM);
    op[0] = r0; op[1] = r1; op[2] = r2; op[3] = r3;
}

extern "C" void kernel_launch(void* const* d_in, const int* in_sizes, int n_in,
                              void* d_out, int out_size) {
    const float* x     = (const float*)d_in[0];
    const float* theta = (const float*)d_in[1];
    const float* w1    = (const float*)d_in[2];
    const float* b1    = (const float*)d_in[3];
    const float* w2    = (const float*)d_in[4];
    const float* b2    = (const float*)d_in[5];
    float* out         = (float*)d_out;

    const int n_tokens = in_sizes[0] / E_DIM;        // B*S
    const int pairs    = n_tokens / TPT;
    const int blocks   = (pairs + THREADS - 1) / THREADS;

    ffq_kernel<<<blocks, THREADS>>>(x, theta, w1, b1, w2, b2, out, n_tokens);
}

// round 3
// speedup vs baseline: 1.0993x; 1.0993x over previous
#include <cuda_runtime.h>

#define E_DIM 8
#define F_DIM 32
#define TPT 2          // tokens per thread
#define THREADS 256

using u64 = unsigned long long;

__device__ __forceinline__ u64 pack2(float lo, float hi) {
    u64 r;
    asm("mov.b64 %0, {%1, %2};" : "=l"(r) : "f"(lo), "f"(hi));
    return r;
}
__device__ __forceinline__ void unpack2(u64 v, float& lo, float& hi) {
    asm("mov.b64 {%0, %1}, %2;" : "=f"(lo), "=f"(hi) : "l"(v));
}
// Packed dual fp32 FMA (Blackwell f32x2 pipe).
__device__ __forceinline__ u64 fma2(u64 a, u64 b, u64 c) {
    u64 d;
    asm("fma.rn.f32x2 %0, %1, %2, %3;" : "=l"(d) : "l"(a), "l"(b), "l"(c));
    return d;
}

__global__ void __launch_bounds__(THREADS, 4)
ffq_kernel(const float* __restrict__ x,
           const float* __restrict__ theta,
           const float* __restrict__ w1,   // [E, F] row-major
           const float* __restrict__ b1,   // [F]
           const float* __restrict__ w2,   // [F, E] row-major
           const float* __restrict__ b2,   // [E]
           float* __restrict__ out,
           int n_tokens)
{
    // W1 stored TRANSPOSED as [f2][i] so the i-inner loop is contiguous
    // and loadable with LDS.128 (ulonglong2). W2 rows are e2-contiguous
    // already. All weight loads are warp-uniform broadcasts (conflict-free).
    __shared__ __align__(16) u64 sw1t[16 * 8];   // [f2][i]
    __shared__ __align__(16) u64 sw2p[32 * 4];   // [f][e2]
    __shared__ __align__(16) u64 sb1[16];
    __shared__ __align__(16) u64 sb2[4];
    __shared__ float sth[E_DIM];

    const int t = threadIdx.x;
    if (t < 128) sw1t[(t & 15) * 8 + (t >> 4)] = ((const u64*)w1)[t];  // transpose
    else         sw2p[t - 128]                 = ((const u64*)w2)[t - 128];
    if (t < 16)       sb1[t]      = ((const u64*)b1)[t];
    else if (t < 20)  sb2[t - 16] = ((const u64*)b2)[t - 16];
    else if (t < 28)  sth[t - 20] = theta[t - 20];
    __syncthreads();

    const long long token0 = ((long long)blockIdx.x * THREADS + t) * TPT;
    if (token0 + 1 >= n_tokens) return;   // exact grid in practice

    // ---- load x for 2 tokens: 64 contiguous bytes ----
    const float4* xp = (const float4*)(x + token0 * E_DIM);
    float4 a0 = xp[0], a1 = xp[1], a2 = xp[2], a3 = xp[3];

    // ---- quantum layer: q = cos(x + theta), pre-packed (q,q) once ----
    u64 q0[E_DIM], q1[E_DIM];
    {
        float c;
        c = __cosf(a0.x + sth[0]); q0[0] = pack2(c, c);
        c = __cosf(a0.y + sth[1]); q0[1] = pack2(c, c);
        c = __cosf(a0.z + sth[2]); q0[2] = pack2(c, c);
        c = __cosf(a0.w + sth[3]); q0[3] = pack2(c, c);
        c = __cosf(a1.x + sth[4]); q0[4] = pack2(c, c);
        c = __cosf(a1.y + sth[5]); q0[5] = pack2(c, c);
        c = __cosf(a1.z + sth[6]); q0[6] = pack2(c, c);
        c = __cosf(a1.w + sth[7]); q0[7] = pack2(c, c);
        c = __cosf(a2.x + sth[0]); q1[0] = pack2(c, c);
        c = __cosf(a2.y + sth[1]); q1[1] = pack2(c, c);
        c = __cosf(a2.z + sth[2]); q1[2] = pack2(c, c);
        c = __cosf(a2.w + sth[3]); q1[3] = pack2(c, c);
        c = __cosf(a3.x + sth[4]); q1[4] = pack2(c, c);
        c = __cosf(a3.y + sth[5]); q1[5] = pack2(c, c);
        c = __cosf(a3.z + sth[6]); q1[6] = pack2(c, c);
        c = __cosf(a3.w + sth[7]); q1[7] = pack2(c, c);
    }

    // ---- fused layer1+layer2: per F-pair, h is transient ----
    u64 o0[E_DIM / 2], o1[E_DIM / 2];
#pragma unroll
    for (int e2 = 0; e2 < E_DIM / 2; e2++) {
        u64 b = sb2[e2];
        o0[e2] = b; o1[e2] = b;
    }

#pragma unroll
    for (int f2 = 0; f2 < F_DIM / 2; f2++) {
        // layer 1: h(f-pair) = b1 + sum_i q_i * w1[i][f-pair]
        u64 h0 = sb1[f2], h1 = h0;
#pragma unroll
        for (int i = 0; i < E_DIM; i += 2) {
            ulonglong2 w = *(const ulonglong2*)&sw1t[f2 * 8 + i];  // LDS.128
            h0 = fma2(q0[i],     w.x, h0);
            h1 = fma2(q1[i],     w.x, h1);
            h0 = fma2(q0[i + 1], w.y, h0);
            h1 = fma2(q1[i + 1], w.y, h1);
        }

        // relu + repack as broadcast pairs
        float h0lo, h0hi, h1lo, h1hi;
        unpack2(h0, h0lo, h0hi);
        unpack2(h1, h1lo, h1hi);
        h0lo = fmaxf(h0lo, 0.0f); h0hi = fmaxf(h0hi, 0.0f);
        h1lo = fmaxf(h1lo, 0.0f); h1hi = fmaxf(h1hi, 0.0f);
        u64 d0lo = pack2(h0lo, h0lo), d0hi = pack2(h0hi, h0hi);
        u64 d1lo = pack2(h1lo, h1lo), d1hi = pack2(h1hi, h1hi);

        // layer 2: o += h_lo * w2[2*f2] + h_hi * w2[2*f2+1]
        const int f = 2 * f2;
        ulonglong2 wla = *(const ulonglong2*)&sw2p[f * 4];        // LDS.128
        ulonglong2 wlb = *(const ulonglong2*)&sw2p[f * 4 + 2];
        ulonglong2 wha = *(const ulonglong2*)&sw2p[f * 4 + 4];
        ulonglong2 whb = *(const ulonglong2*)&sw2p[f * 4 + 6];

        o0[0] = fma2(d0lo, wla.x, o0[0]);
        o0[1] = fma2(d0lo, wla.y, o0[1]);
        o0[2] = fma2(d0lo, wlb.x, o0[2]);
        o0[3] = fma2(d0lo, wlb.y, o0[3]);
        o0[0] = fma2(d0hi, wha.x, o0[0]);
        o0[1] = fma2(d0hi, wha.y, o0[1]);
        o0[2] = fma2(d0hi, whb.x, o0[2]);
        o0[3] = fma2(d0hi, whb.y, o0[3]);

        o1[0] = fma2(d1lo, wla.x, o1[0]);
        o1[1] = fma2(d1lo, wla.y, o1[1]);
        o1[2] = fma2(d1lo, wlb.x, o1[2]);
        o1[3] = fma2(d1lo, wlb.y, o1[3]);
        o1[0] = fma2(d1hi, wha.x, o1[0]);
        o1[1] = fma2(d1hi, wha.y, o1[1]);
        o1[2] = fma2(d1hi, whb.x, o1[2]);
        o1[3] = fma2(d1hi, whb.y, o1[3]);
    }

    // ---- store 2 tokens: 64 contiguous bytes ----
    float4 r0, r1, r2, r3;
    unpack2(o0[0], r0.x, r0.y); unpack2(o0[1], r0.z, r0.w);
    unpack2(o0[2], r1.x, r1.y); unpack2(o0[3], r1.z, r1.w);
    unpack2(o1[0], r2.x, r2.y); unpack2(o1[1], r2.z, r2.w);
    unpack2(o1[2], r3.x, r3.y); unpack2(o1[3], r3.z, r3.w);
    float4* op = (float4*)(out + token0 * E_DIM);
    op[0] = r0; op[1] = r1; op[2] = r2; op[3] = r3;
}

extern "C" void kernel_launch(void* const* d_in, const int* in_sizes, int n_in,
                              void* d_out, int out_size) {
    const float* x     = (const float*)d_in[0];
    const float* theta = (const float*)d_in[1];
    const float* w1    = (const float*)d_in[2];
    const float* b1    = (const float*)d_in[3];
    const float* w2    = (const float*)d_in[4];
    const float* b2    = (const float*)d_in[5];
    float* out         = (float*)d_out;

    const int n_tokens = in_sizes[0] / E_DIM;        // B*S
    const int pairs    = n_tokens / TPT;
    const int blocks   = (pairs + THREADS - 1) / THREADS;

    ffq_kernel<<<blocks, THREADS>>>(x, theta, w1, b1, w2, b2, out, n_tokens);
}

// round 5
// speedup vs baseline: 1.1269x; 1.0250x over previous
#include <cuda_runtime.h>

#define E_DIM 8
#define F_DIM 32
#define TPT 2          // tokens per thread
#define THREADS 256

using u64 = unsigned long long;

// All weights live in constant memory: every access in the unrolled kernel has
// a compile-time-constant address -> LDC/LDCU on the dedicated constant port,
// leaving the L1/shared pipe free for x/out streaming only.
__constant__ __align__(16) float c_w1[E_DIM * F_DIM];  // [E][F] row-major
__constant__ __align__(16) float c_w2[F_DIM * E_DIM];  // [F][E] row-major
__constant__ __align__(16) float c_b1[F_DIM];
__constant__ __align__(16) float c_b2[E_DIM];
__constant__ __align__(16) float c_th[E_DIM];

__device__ __forceinline__ u64 pack2(float lo, float hi) {
    u64 r;
    asm("mov.b64 %0, {%1, %2};" : "=l"(r) : "f"(lo), "f"(hi));
    return r;
}
__device__ __forceinline__ void unpack2(u64 v, float& lo, float& hi) {
    asm("mov.b64 {%0, %1}, %2;" : "=f"(lo), "=f"(hi) : "l"(v));
}
// Packed dual fp32 FMA (Blackwell f32x2 pipe).
__device__ __forceinline__ u64 fma2(u64 a, u64 b, u64 c) {
    u64 d;
    asm("fma.rn.f32x2 %0, %1, %2, %3;" : "=l"(d) : "l"(a), "l"(b), "l"(c));
    return d;
}

__global__ void __launch_bounds__(THREADS, 4)
ffq_kernel(const float* __restrict__ x,
           float* __restrict__ out,
           long long n_tokens)
{
    const long long token0 =
        ((long long)blockIdx.x * THREADS + threadIdx.x) * TPT;
    if (token0 + 1 >= n_tokens) return;   // exact grid in practice

    // ---- load x for 2 tokens: 64 contiguous bytes ----
    const float4* xp = (const float4*)(x + token0 * E_DIM);
    float4 a0 = xp[0], a1 = xp[1], a2 = xp[2], a3 = xp[3];

    // ---- quantum layer: q = cos(x + theta), pre-packed (q,q) ----
    u64 q0[E_DIM], q1[E_DIM];
    {
        float c;
        c = __cosf(a0.x + c_th[0]); q0[0] = pack2(c, c);
        c = __cosf(a0.y + c_th[1]); q0[1] = pack2(c, c);
        c = __cosf(a0.z + c_th[2]); q0[2] = pack2(c, c);
        c = __cosf(a0.w + c_th[3]); q0[3] = pack2(c, c);
        c = __cosf(a1.x + c_th[4]); q0[4] = pack2(c, c);
        c = __cosf(a1.y + c_th[5]); q0[5] = pack2(c, c);
        c = __cosf(a1.z + c_th[6]); q0[6] = pack2(c, c);
        c = __cosf(a1.w + c_th[7]); q0[7] = pack2(c, c);
        c = __cosf(a2.x + c_th[0]); q1[0] = pack2(c, c);
        c = __cosf(a2.y + c_th[1]); q1[1] = pack2(c, c);
        c = __cosf(a2.z + c_th[2]); q1[2] = pack2(c, c);
        c = __cosf(a2.w + c_th[3]); q1[3] = pack2(c, c);
        c = __cosf(a3.x + c_th[4]); q1[4] = pack2(c, c);
        c = __cosf(a3.y + c_th[5]); q1[5] = pack2(c, c);
        c = __cosf(a3.z + c_th[6]); q1[6] = pack2(c, c);
        c = __cosf(a3.w + c_th[7]); q1[7] = pack2(c, c);
    }

    // ---- output accumulators: packed E pairs, init with b2 ----
    u64 o0[E_DIM / 2], o1[E_DIM / 2];
    {
        float4 ba = *(const float4*)&c_b2[0];
        float4 bb = *(const float4*)&c_b2[4];
        o0[0] = pack2(ba.x, ba.y); o0[1] = pack2(ba.z, ba.w);
        o0[2] = pack2(bb.x, bb.y); o0[3] = pack2(bb.z, bb.w);
        o1[0] = o0[0]; o1[1] = o0[1]; o1[2] = o0[2]; o1[3] = o0[3];
    }

    // ---- fused layer1+layer2, 4 F-columns per iteration ----
#pragma unroll
    for (int f4 = 0; f4 < F_DIM / 4; f4++) {
        // layer 1: h for 4 f-values (two packed pairs) per token
        float4 bb = *(const float4*)&c_b1[f4 * 4];          // LDC.128
        u64 hA0 = pack2(bb.x, bb.y), hB0 = pack2(bb.z, bb.w);
        u64 hA1 = hA0, hB1 = hB0;
#pragma unroll
        for (int i = 0; i < E_DIM; i++) {
            float4 w = *(const float4*)&c_w1[i * F_DIM + f4 * 4];  // LDC.128
            u64 wA = pack2(w.x, w.y), wB = pack2(w.z, w.w);
            hA0 = fma2(q0[i], wA, hA0);
            hB0 = fma2(q0[i], wB, hB0);
            hA1 = fma2(q1[i], wA, hA1);
            hB1 = fma2(q1[i], wB, hB1);
        }

        // relu + layer 2 for these 4 f-values
        float h0[4], h1[4];
        unpack2(hA0, h0[0], h0[1]); unpack2(hB0, h0[2], h0[3]);
        unpack2(hA1, h1[0], h1[1]); unpack2(hB1, h1[2], h1[3]);
#pragma unroll
        for (int j = 0; j < 4; j++) {
            const int f = f4 * 4 + j;
            float d0 = fmaxf(h0[j], 0.0f);
            float d1 = fmaxf(h1[j], 0.0f);
            u64 p0 = pack2(d0, d0), p1 = pack2(d1, d1);
            float4 wa = *(const float4*)&c_w2[f * E_DIM];       // LDC.128
            float4 wb = *(const float4*)&c_w2[f * E_DIM + 4];   // LDC.128
            u64 w01 = pack2(wa.x, wa.y), w23 = pack2(wa.z, wa.w);
            u64 w45 = pack2(wb.x, wb.y), w67 = pack2(wb.z, wb.w);
            o0[0] = fma2(p0, w01, o0[0]);
            o0[1] = fma2(p0, w23, o0[1]);
            o0[2] = fma2(p0, w45, o0[2]);
            o0[3] = fma2(p0, w67, o0[3]);
            o1[0] = fma2(p1, w01, o1[0]);
            o1[1] = fma2(p1, w23, o1[1]);
            o1[2] = fma2(p1, w45, o1[2]);
            o1[3] = fma2(p1, w67, o1[3]);
        }
    }

    // ---- store 2 tokens: 64 contiguous bytes ----
    float4 r0, r1, r2, r3;
    unpack2(o0[0], r0.x, r0.y); unpack2(o0[1], r0.z, r0.w);
    unpack2(o0[2], r1.x, r1.y); unpack2(o0[3], r1.z, r1.w);
    unpack2(o1[0], r2.x, r2.y); unpack2(o1[1], r2.z, r2.w);
    unpack2(o1[2], r3.x, r3.y); unpack2(o1[3], r3.z, r3.w);
    float4* op = (float4*)(out + token0 * E_DIM);
    op[0] = r0; op[1] = r1; op[2] = r2; op[3] = r3;
}

extern "C" void kernel_launch(void* const* d_in, const int* in_sizes, int n_in,
                              void* d_out, int out_size) {
    const float* x = (const float*)d_in[0];
    float* out     = (float*)d_out;

    // Stage weights into constant memory (D2D memcpys: graph-capturable).
    cudaMemcpyToSymbolAsync(c_th, d_in[1], E_DIM * sizeof(float), 0,
                            cudaMemcpyDeviceToDevice, 0);
    cudaMemcpyToSymbolAsync(c_w1, d_in[2], E_DIM * F_DIM * sizeof(float), 0,
                            cudaMemcpyDeviceToDevice, 0);
    cudaMemcpyToSymbolAsync(c_b1, d_in[3], F_DIM * sizeof(float), 0,
                            cudaMemcpyDeviceToDevice, 0);
    cudaMemcpyToSymbolAsync(c_w2, d_in[4], F_DIM * E_DIM * sizeof(float), 0,
                            cudaMemcpyDeviceToDevice, 0);
    cudaMemcpyToSymbolAsync(c_b2, d_in[5], E_DIM * sizeof(float), 0,
                            cudaMemcpyDeviceToDevice, 0);

    const long long n_tokens = (long long)in_sizes[0] / E_DIM;  // B*S
    const long long pairs    = n_tokens / TPT;
    const int blocks         = (int)((pairs + THREADS - 1) / THREADS);

    ffq_kernel<<<blocks, THREADS>>>(x, out, n_tokens);
}